// round 14
// baseline (speedup 1.0000x reference)
#include <cuda_runtime.h>
#include <cuda_fp16.h>
#include <stdint.h>

// Problem dims (fixed by the dataset)
#define HID   4096
#define ISZ   11008
#define MROWS 4096   // 2 * 2048

// Scratch (allocation-free rule: __device__ globals)
__device__ __half g_wg[(size_t)HID * ISZ];    // gate W^T: [N=ISZ][K=HID], k contig
__device__ __half g_wu[(size_t)HID * ISZ];    // up  W^T
__device__ __half g_wd[(size_t)ISZ * HID];    // down W^T: [N=HID][K=ISZ]
__device__ __half g_xh[(size_t)MROWS * HID];  // x in fp16
__device__ __half g_gate[(size_t)MROWS * ISZ]; // gate, then SiLU(gate)*up in place

// ---------------------------------------------------------------------------
// helpers
// ---------------------------------------------------------------------------
__device__ __forceinline__ void cp_async16(uint32_t dst, const void* src) {
    asm volatile("cp.async.cg.shared.global [%0], [%1], 16;"
                 :: "r"(dst), "l"(src) : "memory");
}
__device__ __forceinline__ void cp_async_commit() {
    asm volatile("cp.async.commit_group;" ::: "memory");
}
template <int N>
__device__ __forceinline__ void cp_async_wait() {
    asm volatile("cp.async.wait_group %0;" :: "n"(N) : "memory");
}
__device__ __forceinline__ void ldsm_x4(uint32_t& r0, uint32_t& r1,
                                        uint32_t& r2, uint32_t& r3, uint32_t a)
{
    asm volatile("ldmatrix.sync.aligned.m8n8.x4.shared.b16 {%0,%1,%2,%3}, [%4];"
                 : "=r"(r0), "=r"(r1), "=r"(r2), "=r"(r3) : "r"(a));
}

// ---------------------------------------------------------------------------
// Dequant: qw [K/8, N] int32, scales [G, N] fp32, zeros [G, N/8] int32.
// w = q*s - (z+1)*s.  Output W^T: [N][K] fp16, k contiguous.
// ---------------------------------------------------------------------------
__global__ void dequant_kernel(const int* __restrict__ qw,
                               const float* __restrict__ sc,
                               const int* __restrict__ zr,
                               __half* __restrict__ WT, int N, int K)
{
    int n   = blockIdx.y * 256 + threadIdx.x;
    int kw0 = blockIdx.x * 4;
    int g   = (kw0 * 8) >> 7;
    float s  = sc[(size_t)g * N + n];
    int   zw = zr[(size_t)g * (N >> 3) + (n >> 3)];
    float zs = -(float)(((zw >> ((n & 7) * 4)) & 15) + 1) * s;
    __half* dst = WT + (size_t)n * K + kw0 * 8;
#pragma unroll
    for (int i = 0; i < 4; ++i) {
        uint32_t q = (uint32_t)qw[(size_t)(kw0 + i) * N + n];
        __align__(16) __half2 h[4];
#pragma unroll
        for (int p = 0; p < 4; ++p) {
            float f0 = fmaf((float)(q & 15u), s, zs); q >>= 4;
            float f1 = fmaf((float)(q & 15u), s, zs); q >>= 4;
            h[p] = __floats2half2_rn(f0, f1);
        }
        *(int4*)(dst + i * 8) = *(const int4*)h;
    }
}

__global__ void convert_x_kernel(const float4* __restrict__ in,
                                 __half2* __restrict__ out, int n4)
{
    int i = blockIdx.x * blockDim.x + threadIdx.x;
    if (i >= n4) return;
    float4 v = in[i];
    out[2 * i]     = __floats2half2_rn(v.x, v.y);
    out[2 * i + 1] = __floats2half2_rn(v.z, v.w);
}

// ---------------------------------------------------------------------------
// fp16 mma.sync GEMM: C[M,N] = A[M,K] @ W, W^T given as B[N][K] (k contig).
// CTA tile 128x256, BK=64; 256 threads = 8 warps (2m x 4n), warp tile 64x64.
// 4-stage cp.async pipeline, XOR-swizzled smem, ldmatrix.x4 fragments with
// EXPLICIT double buffering (load ks+1 frags before issuing ks MMAs).
// EPI: 0 = store fp16, 1 = SwiGLU fuse (out = SiLU(aux)*acc), 2 = store fp32.
// ---------------------------------------------------------------------------
#define GBM 128
#define GBN 256
#define GBK 64
#define NTHR 256
#define STG_BYTES (GBM * GBK * 2 + GBN * GBK * 2)   // 49152
#define NSTG 4
#define SMEM_BYTES (NSTG * STG_BYTES + 1024)

template <int EPI>
__global__ __launch_bounds__(NTHR, 1)
void gemm_hmma(const __half* __restrict__ A, const __half* __restrict__ B,
               void* __restrict__ Cv, const __half* __restrict__ aux,
               int N, int K)
{
    extern __shared__ char dyn[];
    const uint32_t base = ((uint32_t)__cvta_generic_to_shared(dyn) + 1023u) & ~1023u;

    const int t    = threadIdx.x;
    const int lane = t & 31;
    const int wid  = t >> 5;
    const int warp_m = wid >> 2;     // 0..1
    const int warp_n = wid & 3;      // 0..3
    const int bm = blockIdx.y * GBM;
    const int bn = blockIdx.x * GBN;

    // fill mapping: 16B chunk id = t + i*256 -> row = id>>3, chunk = id&7
    const int fr = t >> 3;           // 0..31
    const int fc = t & 7;
    const __half* Aptr = A + (size_t)(bm + fr) * K + fc * 8;
    const __half* Bptr = B + (size_t)(bn + fr) * K + fc * 8;

    // ldmatrix per-lane bases (XOR swizzle: chunk c of row r at c ^ (r&7))
    const int la_row = warp_m * 64 + (lane & 7) + ((lane >> 3) & 1) * 8;
    const int la_kc  = lane >> 4;
    const int sA7    = la_row & 7;
    const int lb_row = warp_n * 64 + (lane & 7) + ((lane >> 4) & 1) * 8;
    const int lb_kc  = (lane >> 3) & 1;
    const int sB7    = lb_row & 7;

    float acc[4][8][4];
#pragma unroll
    for (int f = 0; f < 4; ++f)
#pragma unroll
        for (int n = 0; n < 8; ++n)
#pragma unroll
            for (int i = 0; i < 4; ++i) acc[f][n][i] = 0.f;

    const int ntiles = K / GBK;

    auto fill = [&](int kt, int stage) {
        const uint32_t sA = base + stage * STG_BYTES;
        const uint32_t sB = sA + GBM * GBK * 2;
        const int koff = kt * GBK;
#pragma unroll
        for (int i = 0; i < 4; ++i) {      // A: 128 rows x 8 chunks
            int r = fr + i * 32;
            cp_async16(sA + (uint32_t)(r * 128 + ((fc ^ (r & 7)) << 4)),
                       Aptr + (size_t)i * 32 * K + koff);
        }
#pragma unroll
        for (int i = 0; i < 8; ++i) {      // B: 256 rows x 8 chunks
            int r = fr + i * 32;
            cp_async16(sB + (uint32_t)(r * 128 + ((fc ^ (r & 7)) << 4)),
                       Bptr + (size_t)i * 32 * K + koff);
        }
        cp_async_commit();
    };

    // prologue: stages 0..2 in flight
    fill(0, 0);
    fill(1, 1);
    fill(2, 2);

    // fragment double buffers
    uint32_t af[2][4][4], bf[2][4][4];

    int stage = 0;
    for (int kt = 0; kt < ntiles; ++kt) {
        cp_async_wait<2>();     // stage of tile kt has landed (<=2 groups pending)
        __syncthreads();        // all warps done with the buffer being refilled next
        if (kt + 3 < ntiles) {
            int ns = stage + 3; if (ns >= NSTG) ns -= NSTG;
            fill(kt + 3, ns);
        }

        const uint32_t sA = base + stage * STG_BYTES;
        const uint32_t sB = sA + GBM * GBK * 2;
        const uint32_t baseA = sA + (uint32_t)(la_row * 128);
        const uint32_t baseB = sB + (uint32_t)(lb_row * 128);

        // preload ks=0 fragments into buffer 0
        {
            const uint32_t offA = (uint32_t)((la_kc ^ sA7) << 4);
            const uint32_t offB = (uint32_t)((lb_kc ^ sB7) << 4);
#pragma unroll
            for (int f = 0; f < 4; ++f)
                ldsm_x4(af[0][f][0], af[0][f][1], af[0][f][2], af[0][f][3],
                        baseA + f * 2048 + offA);
#pragma unroll
            for (int p = 0; p < 4; ++p)
                ldsm_x4(bf[0][p][0], bf[0][p][1], bf[0][p][2], bf[0][p][3],
                        baseB + p * 2048 + offB);
        }

#pragma unroll
        for (int ks = 0; ks < 4; ++ks) {
            const int cur = ks & 1;
            const int nxt = cur ^ 1;
            if (ks < 3) {   // prefetch ks+1 fragments while ks MMAs run
                const uint32_t offA = (uint32_t)((((ks + 1) * 2 + la_kc) ^ sA7) << 4);
                const uint32_t offB = (uint32_t)((((ks + 1) * 2 + lb_kc) ^ sB7) << 4);
#pragma unroll
                for (int f = 0; f < 4; ++f)
                    ldsm_x4(af[nxt][f][0], af[nxt][f][1], af[nxt][f][2], af[nxt][f][3],
                            baseA + f * 2048 + offA);
#pragma unroll
                for (int p = 0; p < 4; ++p)
                    ldsm_x4(bf[nxt][p][0], bf[nxt][p][1], bf[nxt][p][2], bf[nxt][p][3],
                            baseB + p * 2048 + offB);
            }
#pragma unroll
            for (int f = 0; f < 4; ++f)
#pragma unroll
                for (int nf = 0; nf < 8; ++nf) {
                    const int p = nf >> 1;
                    const int h = (nf & 1) * 2;
                    asm volatile(
                        "mma.sync.aligned.m16n8k16.row.col.f32.f16.f16.f32 "
                        "{%0,%1,%2,%3}, {%4,%5,%6,%7}, {%8,%9}, {%0,%1,%2,%3};\n"
                        : "+f"(acc[f][nf][0]), "+f"(acc[f][nf][1]),
                          "+f"(acc[f][nf][2]), "+f"(acc[f][nf][3])
                        : "r"(af[cur][f][0]), "r"(af[cur][f][1]),
                          "r"(af[cur][f][2]), "r"(af[cur][f][3]),
                          "r"(bf[cur][p][h]), "r"(bf[cur][p][h + 1]));
                }
        }
        if (++stage == NSTG) stage = 0;
    }

    // epilogue
#pragma unroll
    for (int f = 0; f < 4; ++f) {
        const int row = bm + warp_m * 64 + f * 16 + (lane >> 2);
#pragma unroll
        for (int nf = 0; nf < 8; ++nf) {
            const int col = bn + warp_n * 64 + nf * 8 + (lane & 3) * 2;
#pragma unroll
            for (int hs = 0; hs < 2; ++hs) {
                const int r = row + hs * 8;
                const float v0 = acc[f][nf][2 * hs];
                const float v1 = acc[f][nf][2 * hs + 1];
                if constexpr (EPI == 0) {
                    *(__half2*)((__half*)Cv + (size_t)r * N + col) =
                        __floats2half2_rn(v0, v1);
                } else if constexpr (EPI == 1) {
                    float2 g = __half22float2(*(const __half2*)(aux + (size_t)r * N + col));
                    float r0 = g.x * v0 / (1.f + __expf(-g.x));
                    float r1 = g.y * v1 / (1.f + __expf(-g.y));
                    *(__half2*)((__half*)Cv + (size_t)r * N + col) =
                        __floats2half2_rn(r0, r1);
                } else {
                    *(float2*)((float*)Cv + (size_t)r * N + col) = make_float2(v0, v1);
                }
            }
        }
    }
}

extern "C" void kernel_launch(void* const* d_in, const int* in_sizes, int n_in,
                              void* d_out, int out_size)
{
    const float* x   = (const float*)d_in[0];   // fp16 upcast to fp32 by harness
    const int*   gqw = (const int*)  d_in[1];
    const float* gsc = (const float*)d_in[2];
    const int*   gze = (const int*)  d_in[3];
    const int*   uqw = (const int*)  d_in[4];
    const float* usc = (const float*)d_in[5];
    const int*   uze = (const int*)  d_in[6];
    const int*   dqw = (const int*)  d_in[7];
    const float* dsc = (const float*)d_in[8];
    const int*   dze = (const int*)  d_in[9];
    float* out = (float*)d_out;                 // fp16 output upcast to fp32

    __half *wg_p, *wu_p, *wd_p, *xh_p, *gate_p;
    cudaGetSymbolAddress((void**)&wg_p,   g_wg);
    cudaGetSymbolAddress((void**)&wu_p,   g_wu);
    cudaGetSymbolAddress((void**)&wd_p,   g_wd);
    cudaGetSymbolAddress((void**)&xh_p,   g_xh);
    cudaGetSymbolAddress((void**)&gate_p, g_gate);

    cudaFuncSetAttribute(gemm_hmma<0>, cudaFuncAttributeMaxDynamicSharedMemorySize, SMEM_BYTES);
    cudaFuncSetAttribute(gemm_hmma<1>, cudaFuncAttributeMaxDynamicSharedMemorySize, SMEM_BYTES);
    cudaFuncSetAttribute(gemm_hmma<2>, cudaFuncAttributeMaxDynamicSharedMemorySize, SMEM_BYTES);

    // 1) one-time prep: x -> fp16, weights -> fp16 (W^T, [N][K])
    {
        int n4 = (MROWS * HID) / 4;
        convert_x_kernel<<<(n4 + 255) / 256, 256>>>((const float4*)x,
                                                    (__half2*)xh_p, n4);
    }
    dequant_kernel<<<dim3(HID / 32, ISZ / 256), 256>>>(gqw, gsc, gze, wg_p, ISZ, HID);
    dequant_kernel<<<dim3(HID / 32, ISZ / 256), 256>>>(uqw, usc, uze, wu_p, ISZ, HID);
    dequant_kernel<<<dim3(ISZ / 32, HID / 256), 256>>>(dqw, dsc, dze, wd_p, HID, ISZ);

    // 2) GEMMs
    dim3 blk(NTHR);
    dim3 grid1(ISZ / GBN, MROWS / GBM);   // 43 x 32
    gemm_hmma<0><<<grid1, blk, SMEM_BYTES>>>(xh_p, wg_p, gate_p, nullptr, ISZ, HID);
    // up-GEMM with fused SwiGLU: gate_p := SiLU(gate_p) * (x @ Wu)
    gemm_hmma<1><<<grid1, blk, SMEM_BYTES>>>(xh_p, wu_p, gate_p, gate_p, ISZ, HID);

    dim3 grid2(HID / GBN, MROWS / GBM);   // 16 x 32
    gemm_hmma<2><<<grid2, blk, SMEM_BYTES>>>(gate_p, wd_p, out, nullptr, HID, ISZ);
}

// round 15
// speedup vs baseline: 1.0674x; 1.0674x over previous
#include <cuda_runtime.h>
#include <cuda_fp16.h>
#include <stdint.h>

// Problem dims (fixed by the dataset)
#define HID   4096
#define ISZ   11008
#define MROWS 4096   // 2 * 2048

// Scratch (allocation-free rule: __device__ globals)
__device__ __half g_wg[(size_t)HID * ISZ];    // gate W^T: [N=ISZ][K=HID], k contig
__device__ __half g_wu[(size_t)HID * ISZ];    // up  W^T
__device__ __half g_wd[(size_t)ISZ * HID];    // down W^T: [N=HID][K=ISZ]
__device__ __half g_xh[(size_t)MROWS * HID];  // x in fp16
__device__ __half g_gate[(size_t)MROWS * ISZ]; // gate, then SiLU(gate)*up in place

// ---------------------------------------------------------------------------
// helpers
// ---------------------------------------------------------------------------
__device__ __forceinline__ void cp_async16(uint32_t dst, const void* src) {
    asm volatile("cp.async.cg.shared.global [%0], [%1], 16;"
                 :: "r"(dst), "l"(src) : "memory");
}
__device__ __forceinline__ void cp_async_commit() {
    asm volatile("cp.async.commit_group;" ::: "memory");
}
template <int N>
__device__ __forceinline__ void cp_async_wait() {
    asm volatile("cp.async.wait_group %0;" :: "n"(N) : "memory");
}
__device__ __forceinline__ void ldsm_x4(uint32_t& r0, uint32_t& r1,
                                        uint32_t& r2, uint32_t& r3, uint32_t a)
{
    asm volatile("ldmatrix.sync.aligned.m8n8.x4.shared.b16 {%0,%1,%2,%3}, [%4];"
                 : "=r"(r0), "=r"(r1), "=r"(r2), "=r"(r3) : "r"(a));
}

// ---------------------------------------------------------------------------
// Dequant: qw [K/8, N] int32, scales [G, N] fp32, zeros [G, N/8] int32.
// w = q*s - (z+1)*s.  Output W^T: [N][K] fp16, k contiguous.
// ---------------------------------------------------------------------------
__global__ void dequant_kernel(const int* __restrict__ qw,
                               const float* __restrict__ sc,
                               const int* __restrict__ zr,
                               __half* __restrict__ WT, int N, int K)
{
    int n   = blockIdx.y * 256 + threadIdx.x;
    int kw0 = blockIdx.x * 4;
    int g   = (kw0 * 8) >> 7;
    float s  = sc[(size_t)g * N + n];
    int   zw = zr[(size_t)g * (N >> 3) + (n >> 3)];
    float zs = -(float)(((zw >> ((n & 7) * 4)) & 15) + 1) * s;
    __half* dst = WT + (size_t)n * K + kw0 * 8;
#pragma unroll
    for (int i = 0; i < 4; ++i) {
        uint32_t q = (uint32_t)qw[(size_t)(kw0 + i) * N + n];
        __align__(16) __half2 h[4];
#pragma unroll
        for (int p = 0; p < 4; ++p) {
            float f0 = fmaf((float)(q & 15u), s, zs); q >>= 4;
            float f1 = fmaf((float)(q & 15u), s, zs); q >>= 4;
            h[p] = __floats2half2_rn(f0, f1);
        }
        *(int4*)(dst + i * 8) = *(const int4*)h;
    }
}

__global__ void convert_x_kernel(const float4* __restrict__ in,
                                 __half2* __restrict__ out, int n4)
{
    int i = blockIdx.x * blockDim.x + threadIdx.x;
    if (i >= n4) return;
    float4 v = in[i];
    out[2 * i]     = __floats2half2_rn(v.x, v.y);
    out[2 * i + 1] = __floats2half2_rn(v.z, v.w);
}

// ---------------------------------------------------------------------------
// fp16 mma.sync GEMM: C[M,N] = A[M,K] @ W, W^T given as B[N][K] (k contig).
// CTA tile 128x256, BK=64; 512 threads = 16 warps (2m x 8n), warp tile 64x32.
// 3-stage cp.async pipeline, XOR-swizzled smem, ldmatrix.x4 fragments.
// Anti-convoy: each warp walks the 4 ks-steps in rotated order (wid&3) so
// LSU(LDSM) and tensor(MMA) phases of different warps overlap instead of
// alternating in lockstep after each barrier.
// EPI: 0 = store fp16, 1 = SwiGLU fuse (out = SiLU(aux)*acc), 2 = store fp32.
// ---------------------------------------------------------------------------
#define GBM 128
#define GBN 256
#define GBK 64
#define NTHR 512
#define STG_BYTES (GBM * GBK * 2 + GBN * GBK * 2)   // 49152
#define SMEM_BYTES (3 * STG_BYTES + 1024)

template <int EPI>
__global__ __launch_bounds__(NTHR, 1)
void gemm_hmma(const __half* __restrict__ A, const __half* __restrict__ B,
               void* __restrict__ Cv, const __half* __restrict__ aux,
               int N, int K)
{
    extern __shared__ char dyn[];
    const uint32_t base = ((uint32_t)__cvta_generic_to_shared(dyn) + 1023u) & ~1023u;

    const int t    = threadIdx.x;
    const int lane = t & 31;
    const int wid  = t >> 5;
    const int warp_m = wid >> 3;     // 0..1
    const int warp_n = wid & 7;      // 0..7
    const int kphase = wid & 3;      // anti-convoy rotation
    const int bm = blockIdx.y * GBM;
    const int bn = blockIdx.x * GBN;

    // fill mapping: 16B chunk id = t + i*512 -> row = id>>3, chunk = id&7
    const int fr = t >> 3;           // 0..63
    const int fc = t & 7;
    const __half* Aptr = A + (size_t)(bm + fr) * K + fc * 8;
    const __half* Bptr = B + (size_t)(bn + fr) * K + fc * 8;

    // ldmatrix per-lane bases (XOR swizzle: chunk c of row r at c ^ (r&7))
    const int la_row = warp_m * 64 + (lane & 7) + ((lane >> 3) & 1) * 8;
    const int la_kc  = lane >> 4;
    const int sA7    = la_row & 7;
    const int lb_row = warp_n * 32 + (lane & 7) + ((lane >> 4) & 1) * 8;
    const int lb_kc  = (lane >> 3) & 1;
    const int sB7    = lb_row & 7;

    float acc[4][4][4];
#pragma unroll
    for (int f = 0; f < 4; ++f)
#pragma unroll
        for (int n = 0; n < 4; ++n)
#pragma unroll
            for (int i = 0; i < 4; ++i) acc[f][n][i] = 0.f;

    const int ntiles = K / GBK;

    auto fill = [&](int kt, int stage) {
        const uint32_t sA = base + stage * STG_BYTES;
        const uint32_t sB = sA + GBM * GBK * 2;
        const int koff = kt * GBK;
#pragma unroll
        for (int i = 0; i < 2; ++i) {      // A: 128 rows x 8 chunks
            int r = fr + i * 64;
            cp_async16(sA + (uint32_t)(r * 128 + ((fc ^ (r & 7)) << 4)),
                       Aptr + (size_t)i * 64 * K + koff);
        }
#pragma unroll
        for (int i = 0; i < 4; ++i) {      // B: 256 rows x 8 chunks
            int r = fr + i * 64;
            cp_async16(sB + (uint32_t)(r * 128 + ((fc ^ (r & 7)) << 4)),
                       Bptr + (size_t)i * 64 * K + koff);
        }
        cp_async_commit();
    };

    // prologue: stages 0 and 1 in flight
    fill(0, 0);
    fill(1, 1);

    int stage = 0;
    for (int kt = 0; kt < ntiles; ++kt) {
        cp_async_wait<1>();     // stage of tile kt has landed
        __syncthreads();        // everyone done computing tile kt-1 (its buffer = next fill target)
        if (kt + 2 < ntiles) {
            int ns = stage + 2; if (ns >= 3) ns -= 3;
            fill(kt + 2, ns);
        }

        const uint32_t sA = base + stage * STG_BYTES;
        const uint32_t sB = sA + GBM * GBK * 2;
        const uint32_t baseA = sA + (uint32_t)(la_row * 128);
        const uint32_t baseB = sB + (uint32_t)(lb_row * 128);

#pragma unroll
        for (int ks0 = 0; ks0 < 4; ++ks0) {
            const int ks = (ks0 + kphase) & 3;   // rotated per-warp ks order
            const uint32_t offA = (uint32_t)(((ks * 2 + la_kc) ^ sA7) << 4);
            const uint32_t offB = (uint32_t)(((ks * 2 + lb_kc) ^ sB7) << 4);
            uint32_t af[4][4], bf[4][2];
            // issue order: A0, B0 (operands of the first MMAs) first
            ldsm_x4(af[0][0], af[0][1], af[0][2], af[0][3], baseA + 0 * 2048 + offA);
            ldsm_x4(bf[0][0], bf[0][1], bf[1][0], bf[1][1], baseB + 0 * 2048 + offB);
            ldsm_x4(af[1][0], af[1][1], af[1][2], af[1][3], baseA + 1 * 2048 + offA);
            ldsm_x4(af[2][0], af[2][1], af[2][2], af[2][3], baseA + 2 * 2048 + offA);
            ldsm_x4(af[3][0], af[3][1], af[3][2], af[3][3], baseA + 3 * 2048 + offA);
            ldsm_x4(bf[2][0], bf[2][1], bf[3][0], bf[3][1], baseB + 1 * 2048 + offB);
            // nf outer, f inner: bf[2]/bf[3] not needed until MMA #9
#pragma unroll
            for (int nf = 0; nf < 4; ++nf)
#pragma unroll
                for (int f = 0; f < 4; ++f) {
                    asm volatile(
                        "mma.sync.aligned.m16n8k16.row.col.f32.f16.f16.f32 "
                        "{%0,%1,%2,%3}, {%4,%5,%6,%7}, {%8,%9}, {%0,%1,%2,%3};\n"
                        : "+f"(acc[f][nf][0]), "+f"(acc[f][nf][1]),
                          "+f"(acc[f][nf][2]), "+f"(acc[f][nf][3])
                        : "r"(af[f][0]), "r"(af[f][1]),
                          "r"(af[f][2]), "r"(af[f][3]),
                          "r"(bf[nf][0]), "r"(bf[nf][1]));
                }
        }
        if (++stage == 3) stage = 0;
    }

    // epilogue
#pragma unroll
    for (int f = 0; f < 4; ++f) {
        const int row = bm + warp_m * 64 + f * 16 + (lane >> 2);
#pragma unroll
        for (int nf = 0; nf < 4; ++nf) {
            const int col = bn + warp_n * 32 + nf * 8 + (lane & 3) * 2;
#pragma unroll
            for (int hs = 0; hs < 2; ++hs) {
                const int r = row + hs * 8;
                const float v0 = acc[f][nf][2 * hs];
                const float v1 = acc[f][nf][2 * hs + 1];
                if constexpr (EPI == 0) {
                    *(__half2*)((__half*)Cv + (size_t)r * N + col) =
                        __floats2half2_rn(v0, v1);
                } else if constexpr (EPI == 1) {
                    float2 g = __half22float2(*(const __half2*)(aux + (size_t)r * N + col));
                    float r0 = g.x * v0 / (1.f + __expf(-g.x));
                    float r1 = g.y * v1 / (1.f + __expf(-g.y));
                    *(__half2*)((__half*)Cv + (size_t)r * N + col) =
                        __floats2half2_rn(r0, r1);
                } else {
                    *(float2*)((float*)Cv + (size_t)r * N + col) = make_float2(v0, v1);
                }
            }
        }
    }
}

extern "C" void kernel_launch(void* const* d_in, const int* in_sizes, int n_in,
                              void* d_out, int out_size)
{
    const float* x   = (const float*)d_in[0];   // fp16 upcast to fp32 by harness
    const int*   gqw = (const int*)  d_in[1];
    const float* gsc = (const float*)d_in[2];
    const int*   gze = (const int*)  d_in[3];
    const int*   uqw = (const int*)  d_in[4];
    const float* usc = (const float*)d_in[5];
    const int*   uze = (const int*)  d_in[6];
    const int*   dqw = (const int*)  d_in[7];
    const float* dsc = (const float*)d_in[8];
    const int*   dze = (const int*)  d_in[9];
    float* out = (float*)d_out;                 // fp16 output upcast to fp32

    __half *wg_p, *wu_p, *wd_p, *xh_p, *gate_p;
    cudaGetSymbolAddress((void**)&wg_p,   g_wg);
    cudaGetSymbolAddress((void**)&wu_p,   g_wu);
    cudaGetSymbolAddress((void**)&wd_p,   g_wd);
    cudaGetSymbolAddress((void**)&xh_p,   g_xh);
    cudaGetSymbolAddress((void**)&gate_p, g_gate);

    cudaFuncSetAttribute(gemm_hmma<0>, cudaFuncAttributeMaxDynamicSharedMemorySize, SMEM_BYTES);
    cudaFuncSetAttribute(gemm_hmma<1>, cudaFuncAttributeMaxDynamicSharedMemorySize, SMEM_BYTES);
    cudaFuncSetAttribute(gemm_hmma<2>, cudaFuncAttributeMaxDynamicSharedMemorySize, SMEM_BYTES);

    // 1) one-time prep: x -> fp16, weights -> fp16 (W^T, [N][K])
    {
        int n4 = (MROWS * HID) / 4;
        convert_x_kernel<<<(n4 + 255) / 256, 256>>>((const float4*)x,
                                                    (__half2*)xh_p, n4);
    }
    dequant_kernel<<<dim3(HID / 32, ISZ / 256), 256>>>(gqw, gsc, gze, wg_p, ISZ, HID);
    dequant_kernel<<<dim3(HID / 32, ISZ / 256), 256>>>(uqw, usc, uze, wu_p, ISZ, HID);
    dequant_kernel<<<dim3(ISZ / 32, HID / 256), 256>>>(dqw, dsc, dze, wd_p, HID, ISZ);

    // 2) GEMMs
    dim3 blk(NTHR);
    dim3 grid1(ISZ / GBN, MROWS / GBM);   // 43 x 32
    gemm_hmma<0><<<grid1, blk, SMEM_BYTES>>>(xh_p, wg_p, gate_p, nullptr, ISZ, HID);
    // up-GEMM with fused SwiGLU: gate_p := SiLU(gate_p) * (x @ Wu)
    gemm_hmma<1><<<grid1, blk, SMEM_BYTES>>>(xh_p, wu_p, gate_p, gate_p, ISZ, HID);

    dim3 grid2(HID / GBN, MROWS / GBM);   // 16 x 32
    gemm_hmma<2><<<grid2, blk, SMEM_BYTES>>>(gate_p, wd_p, out, nullptr, HID, ISZ);
}